// round 1
// baseline (speedup 1.0000x reference)
#include <cuda_runtime.h>
#include <math.h>

// Problem constants (match reference)
#define BB   4
#define VV   20000
#define PP   400000
#define NNN  50000
#define MPP  32
#define MMG  64            // grid M
#define GAMMA_F 10.0f
#define KSOFT   2.0f
#define THRESH_F 1.0f
#define W_WL_F  1.0f
#define W_CONG_F 0.5f

#define NET_BLOCKS 148     // blocks per batch for phase B

// ---------------- scratch (device globals; no allocation allowed) ----------
__device__ float2 g_pin_pos[BB * PP];          // 12.8 MB
__device__ float  g_rudy[BB][MMG * MMG];       // 64 KB
__device__ float  g_hpwl[BB];

// ---------------------------------------------------------------------------
__global__ void zero_kernel() {
    int idx = blockIdx.x * blockDim.x + threadIdx.x;
    int stride = gridDim.x * blockDim.x;
    float* r = &g_rudy[0][0];
    for (int i = idx; i < BB * MMG * MMG; i += stride) r[i] = 0.0f;
    if (idx < BB) g_hpwl[idx] = 0.0f;
}

// ---------------------------------------------------------------------------
// Phase A: pin positions  pin_pos[b,p] = positions[b,m] + R(rot[b,m]) @ off[p]
__global__ __launch_bounds__(256) void pin_pos_kernel(
    const float* __restrict__ positions,      // (B,V,2)
    const int*   __restrict__ pin_to_macro,   // (P,)
    const float* __restrict__ pin_offsets,    // (P,2)
    const float* __restrict__ rot_onehot)     // (B,V,4)
{
    int idx = blockIdx.x * blockDim.x + threadIdx.x;
    if (idx >= BB * PP) return;
    int b = idx / PP;
    int p = idx - b * PP;
    int m = pin_to_macro[p];
    float2 pos = ((const float2*)positions)[b * VV + m];
    float4 oh  = ((const float4*)rot_onehot)[b * VV + m];
    float2 off = ((const float2*)pin_offsets)[p];
    // R = oh0*I + oh1*[[0,-1],[1,0]] + oh2*(-I) + oh3*[[0,1],[-1,0]]
    float c = oh.x - oh.z;     // cos-like
    float s = oh.y - oh.w;     // sin-like
    float2 pp;
    pp.x = pos.x + c * off.x - s * off.y;
    pp.y = pos.y + s * off.x + c * off.y;
    g_pin_pos[idx] = pp;
}

// ---------------------------------------------------------------------------
__device__ __forceinline__ float fast_sig(float x) {
    return __fdividef(1.0f, 1.0f + __expf(-x));
}

// Phase B: per-net HPWL (soft) + bbox + rank-1 RUDY accumulation.
// One warp per net; block of 8 warps does a rank-8 update of a 64x64 tile
// held in registers (each thread owns a 4x4 subtile).
__global__ __launch_bounds__(256) void net_kernel(
    const int*   __restrict__ net_to_pin,     // (NN,MP)
    const float* __restrict__ net_weights)    // (NN,)
{
    __shared__ float Xs[8][MMG];
    __shared__ float Ys[8][MMG];

    const int b    = blockIdx.y;
    const int tid  = threadIdx.x;
    const int w    = tid >> 5;
    const int lane = tid & 31;
    const int ty   = tid >> 4;       // 0..15
    const int tx   = tid & 15;       // 0..15

    const int netsPerBlock = (NNN + gridDim.x - 1) / gridDim.x;   // 338
    const int n0 = blockIdx.x * netsPerBlock;
    const int n1 = min(n0 + netsPerBlock, NNN);

    float acc[4][4];
#pragma unroll
    for (int a = 0; a < 4; a++)
#pragma unroll
        for (int c = 0; c < 4; c++) acc[a][c] = 0.0f;

    float hp = 0.0f;   // meaningful on lane 0 of each warp

    for (int base = n0; base < n1; base += 8) {
        const int n = base + w;
        const bool active = (n < n1);

        float px = 0.0f, py = 0.0f;
        bool valid = false;
        if (active) {
            int j = net_to_pin[n * MPP + lane];
            valid = (j >= 0);
            int sj = j < 0 ? 0 : j;
            float2 pp = g_pin_pos[b * PP + sj];
            px = pp.x; py = pp.y;
        }

        float vxM = valid ? px : -1e9f;
        float vxm = valid ? px :  1e9f;
        float vyM = valid ? py : -1e9f;
        float vym = valid ? py :  1e9f;
#pragma unroll
        for (int o = 16; o > 0; o >>= 1) {
            vxM = fmaxf(vxM, __shfl_xor_sync(0xffffffffu, vxM, o));
            vxm = fminf(vxm, __shfl_xor_sync(0xffffffffu, vxm, o));
            vyM = fmaxf(vyM, __shfl_xor_sync(0xffffffffu, vyM, o));
            vym = fminf(vym, __shfl_xor_sync(0xffffffffu, vym, o));
        }

        // softmax-LSE sums (invalid lanes contribute exactly 0, matching
        // the reference's -1e9 masking which underflows to 0 after exp)
        float exM = valid ? __expf( GAMMA_F * (px - vxM)) : 0.0f;
        float exm = valid ? __expf(-GAMMA_F * (px - vxm)) : 0.0f;
        float eyM = valid ? __expf( GAMMA_F * (py - vyM)) : 0.0f;
        float eym = valid ? __expf(-GAMMA_F * (py - vym)) : 0.0f;
#pragma unroll
        for (int o = 16; o > 0; o >>= 1) {
            exM += __shfl_xor_sync(0xffffffffu, exM, o);
            exm += __shfl_xor_sync(0xffffffffu, exm, o);
            eyM += __shfl_xor_sync(0xffffffffu, eyM, o);
            eym += __shfl_xor_sync(0xffffffffu, eym, o);
        }

        if (active && lane == 0) {
            float lseMx = vxM + __logf(exM) * (1.0f / GAMMA_F);
            float lsemx = vxm - __logf(exm) * (1.0f / GAMMA_F);
            float lseMy = vyM + __logf(eyM) * (1.0f / GAMMA_F);
            float lsemy = vym - __logf(eym) * (1.0f / GAMMA_F);
            float wl = (lseMx - lsemx) + (lseMy - lsemy);
            hp += wl * net_weights[n];
        }

        // bbox in grid coords
        float bxm = (vxm + 1.0f) * 0.5f * (MMG - 1);
        float bxM = (vxM + 1.0f) * 0.5f * (MMG - 1);
        float bym = (vym + 1.0f) * 0.5f * (MMG - 1);
        float byM = (vyM + 1.0f) * 0.5f * (MMG - 1);
        float bsize = fmaxf((bxM - bxm + 1.0f) * (byM - bym + 1.0f), 1.0f);
        float inv_bs = __fdividef(1.0f, bsize);

#pragma unroll
        for (int t = 0; t < 2; t++) {
            int gi = lane + t * 32;
            float g = (float)gi;
            float xv = 0.0f, yv = 0.0f;
            if (active) {
                xv = fast_sig(KSOFT * (g - bxm + 0.5f)) *
                     fast_sig(KSOFT * (bxM - g + 0.5f));
                yv = fast_sig(KSOFT * (g - bym + 0.5f)) *
                     fast_sig(KSOFT * (byM - g + 0.5f)) * inv_bs;
            }
            Xs[w][gi] = xv;
            Ys[w][gi] = yv;
        }
        __syncthreads();

        // rank-8 update of 64x64 tile
#pragma unroll
        for (int k = 0; k < 8; k++) {
            float4 yv = *(const float4*)&Ys[k][ty * 4];
            float4 xv = *(const float4*)&Xs[k][tx * 4];
            acc[0][0] = fmaf(yv.x, xv.x, acc[0][0]);
            acc[0][1] = fmaf(yv.x, xv.y, acc[0][1]);
            acc[0][2] = fmaf(yv.x, xv.z, acc[0][2]);
            acc[0][3] = fmaf(yv.x, xv.w, acc[0][3]);
            acc[1][0] = fmaf(yv.y, xv.x, acc[1][0]);
            acc[1][1] = fmaf(yv.y, xv.y, acc[1][1]);
            acc[1][2] = fmaf(yv.y, xv.z, acc[1][2]);
            acc[1][3] = fmaf(yv.y, xv.w, acc[1][3]);
            acc[2][0] = fmaf(yv.z, xv.x, acc[2][0]);
            acc[2][1] = fmaf(yv.z, xv.y, acc[2][1]);
            acc[2][2] = fmaf(yv.z, xv.z, acc[2][2]);
            acc[2][3] = fmaf(yv.z, xv.w, acc[2][3]);
            acc[3][0] = fmaf(yv.w, xv.x, acc[3][0]);
            acc[3][1] = fmaf(yv.w, xv.y, acc[3][1]);
            acc[3][2] = fmaf(yv.w, xv.z, acc[3][2]);
            acc[3][3] = fmaf(yv.w, xv.w, acc[3][3]);
        }
        __syncthreads();
    }

    // flush tile partials
#pragma unroll
    for (int a = 0; a < 4; a++)
#pragma unroll
        for (int c = 0; c < 4; c++)
            atomicAdd(&g_rudy[b][(ty * 4 + a) * MMG + tx * 4 + c], acc[a][c]);

    if (lane == 0) atomicAdd(&g_hpwl[b], hp);
}

// ---------------------------------------------------------------------------
// Phase C: 7x7 Gaussian smooth (zero-padded), overflow penalty, final combine.
__global__ __launch_bounds__(256) void conv_kernel(float* __restrict__ out)
{
    __shared__ float tile[MMG][MMG];
    __shared__ float red[256];
    const int b = blockIdx.x;
    const int tid = threadIdx.x;

    for (int i = tid; i < MMG * MMG; i += 256)
        tile[i >> 6][i & 63] = g_rudy[b][i];
    __syncthreads();

    // Gaussian 1D taps: exp(-x^2 / (2*1.5^2)), x=-3..3
    const float g1[7] = {0.13533528f, 0.41111229f, 0.80073740f, 1.0f,
                         0.80073740f, 0.41111229f, 0.13533528f};
    float s1 = 0.0f;
#pragma unroll
    for (int i = 0; i < 7; i++) s1 += g1[i];
    const float inv_norm = __fdividef(1.0f, s1 * s1);

    float pen = 0.0f;
    for (int cell = tid; cell < MMG * MMG; cell += 256) {
        int i = cell >> 6;
        int j = cell & 63;
        float s = 0.0f;
#pragma unroll
        for (int di = -3; di <= 3; di++) {
            int ii = i + di;
            if (ii < 0 || ii >= MMG) continue;
            float wi = g1[di + 3];
            float rs = 0.0f;
#pragma unroll
            for (int dj = -3; dj <= 3; dj++) {
                int jj = j + dj;
                if (jj < 0 || jj >= MMG) continue;
                rs = fmaf(g1[dj + 3], tile[ii][jj], rs);
            }
            s = fmaf(wi, rs, s);
        }
        s *= inv_norm;
        float ov = fmaxf(s - THRESH_F, 0.0f);
        pen = fmaf(ov, ov, pen);
    }

    red[tid] = pen;
    __syncthreads();
    for (int o = 128; o > 0; o >>= 1) {
        if (tid < o) red[tid] += red[tid + o];
        __syncthreads();
    }
    if (tid == 0)
        out[b] = W_WL_F * g_hpwl[b] + W_CONG_F * red[0];
}

// ---------------------------------------------------------------------------
extern "C" void kernel_launch(void* const* d_in, const int* in_sizes, int n_in,
                              void* d_out, int out_size)
{
    const float* positions   = nullptr;
    const int*   net_to_pin  = nullptr;
    const int*   pin_to_macro= nullptr;
    const float* pin_offsets = nullptr;
    const float* rot_onehot  = nullptr;
    const float* net_weights = nullptr;

    for (int i = 0; i < n_in; i++) {
        switch (in_sizes[i]) {
            case BB * VV * 2:   positions    = (const float*)d_in[i]; break; // 160000
            case NNN * MPP:     net_to_pin   = (const int*)  d_in[i]; break; // 1600000
            case PP:            pin_to_macro = (const int*)  d_in[i]; break; // 400000
            case PP * 2:        pin_offsets  = (const float*)d_in[i]; break; // 800000
            case BB * VV * 4:   rot_onehot   = (const float*)d_in[i]; break; // 320000
            case NNN:           net_weights  = (const float*)d_in[i]; break; // 50000
        }
    }

    zero_kernel<<<64, 256>>>();
    pin_pos_kernel<<<(BB * PP + 255) / 256, 256>>>(positions, pin_to_macro,
                                                   pin_offsets, rot_onehot);
    net_kernel<<<dim3(NET_BLOCKS, BB), 256>>>(net_to_pin, net_weights);
    conv_kernel<<<BB, 256>>>((float*)d_out);
}

// round 2
// speedup vs baseline: 1.1349x; 1.1349x over previous
#include <cuda_runtime.h>
#include <math.h>

// Problem constants (match reference)
#define BB   4
#define VV   20000
#define PP   400000
#define NNN  50000
#define MPP  32
#define MMG  64            // grid M
#define THRESH_F 1.0f
#define W_CONG_F 0.5f

#define NET_BLOCKS 148     // blocks per batch for phase B

// log2(e) folded constants
#define GL2  14.426950408889634f   // GAMMA * log2(e),  GAMMA = 10
#define KL2  2.8853900817779268f   // K_SOFT * log2(e), K_SOFT = 2
#define INV_GAMMA 0.1f

// ---------------- scratch (device globals; no allocation allowed) ----------
__device__ float2 g_pin_pos[BB * PP];          // 12.8 MB
__device__ float  g_rudy[BB][MMG * MMG];       // 64 KB
__device__ float  g_hpwl[BB];
__device__ float  g_pen[BB];

// monotonic float <-> uint encoding for REDUX min/max on floats
__device__ __forceinline__ unsigned fenc(float x) {
    unsigned b = __float_as_uint(x);
    return b ^ (((unsigned)((int)b >> 31)) | 0x80000000u);
}
__device__ __forceinline__ float fdec(unsigned u) {
    unsigned b = u ^ ((~(unsigned)((int)u >> 31)) | 0x80000000u);
    return __uint_as_float(b);
}

// ---------------------------------------------------------------------------
// Phase A: pin positions (also zeroes the accumulators for this call)
__global__ __launch_bounds__(256) void pin_pos_kernel(
    const float* __restrict__ positions,      // (B,V,2)
    const int*   __restrict__ pin_to_macro,   // (P,)
    const float* __restrict__ pin_offsets,    // (P,2)
    const float* __restrict__ rot_onehot)     // (B,V,4)
{
    int idx = blockIdx.x * blockDim.x + threadIdx.x;

    // zero accumulators (first 64 blocks cover 4*64*64 floats)
    if (blockIdx.x < 64) {
        (&g_rudy[0][0])[idx] = 0.0f;
        if (idx < BB) { g_hpwl[idx] = 0.0f; g_pen[idx] = 0.0f; }
    }

    if (idx >= BB * PP) return;
    int b = idx / PP;
    int p = idx - b * PP;
    int m = pin_to_macro[p];
    float2 pos = ((const float2*)positions)[b * VV + m];
    float4 oh  = ((const float4*)rot_onehot)[b * VV + m];
    float2 off = ((const float2*)pin_offsets)[p];
    float c = oh.x - oh.z;
    float s = oh.y - oh.w;
    float2 pp;
    pp.x = pos.x + c * off.x - s * off.y;
    pp.y = pos.y + s * off.x + c * off.y;
    g_pin_pos[idx] = pp;
}

// ---------------------------------------------------------------------------
// Phase B: per-net soft-HPWL + bbox + rank-8 RUDY accumulation.
__global__ __launch_bounds__(256) void net_kernel(
    const int*   __restrict__ net_to_pin,     // (NN,MP)
    const float* __restrict__ net_weights)    // (NN,)
{
    __shared__ float Xs[8][MMG];
    __shared__ float Ys[8][MMG];

    const int b    = blockIdx.y;
    const int tid  = threadIdx.x;
    const int w    = tid >> 5;
    const int lane = tid & 31;
    const int ty   = tid >> 4;       // 0..15
    const int tx   = tid & 15;       // 0..15

    const int netsPerBlock = (NNN + NET_BLOCKS - 1) / NET_BLOCKS;   // 338
    const int n0 = blockIdx.x * netsPerBlock;
    const int n1 = min(n0 + netsPerBlock, NNN);

    float acc[4][4];
#pragma unroll
    for (int a = 0; a < 4; a++)
#pragma unroll
        for (int c = 0; c < 4; c++) acc[a][c] = 0.0f;

    float hp = 0.0f;   // meaningful on lane 0 of each warp

    for (int base = n0; base < n1; base += 8) {
        const int n = base + w;
        const bool active = (n < n1);

        float vxM = 0.f, vxm = 0.f, vyM = 0.f, vym = 0.f;
        float bxm = 0.f, bxM = 0.f, bym = 0.f, byM = 0.f, inv_bs = 0.f;

        if (active) {
            int j = net_to_pin[n * MPP + lane];
            bool valid = (j >= 0);
            int sj = j < 0 ? 0 : j;
            float2 pp = g_pin_pos[b * PP + sj];
            float px = pp.x, py = pp.y;

            // max/min via single-instruction REDUX on monotonic encodings
            unsigned ex = fenc(px);
            unsigned ey = fenc(py);
            vxM = fdec(__reduce_max_sync(0xffffffffu, valid ? ex : 0u));
            vxm = fdec(__reduce_min_sync(0xffffffffu, valid ? ex : 0xffffffffu));
            vyM = fdec(__reduce_max_sync(0xffffffffu, valid ? ey : 0u));
            vym = fdec(__reduce_min_sync(0xffffffffu, valid ? ey : 0xffffffffu));

            // LSE sums (invalid lanes contribute exactly 0, matching the
            // reference's -1e9 masking which underflows to 0 after exp)
            float exM = valid ? exp2f( GL2 * (px - vxM)) : 0.0f;
            float exm = valid ? exp2f(-GL2 * (px - vxm)) : 0.0f;
            float eyM = valid ? exp2f( GL2 * (py - vyM)) : 0.0f;
            float eym = valid ? exp2f(-GL2 * (py - vym)) : 0.0f;
#pragma unroll
            for (int o = 16; o > 0; o >>= 1) {
                exM += __shfl_xor_sync(0xffffffffu, exM, o);
                exm += __shfl_xor_sync(0xffffffffu, exm, o);
                eyM += __shfl_xor_sync(0xffffffffu, eyM, o);
                eym += __shfl_xor_sync(0xffffffffu, eym, o);
            }

            if (lane == 0) {
                float wl = (vxM - vxm) + (vyM - vym)
                         + (__log2f(exM) + __log2f(exm)
                          + __log2f(eyM) + __log2f(eym)) * (INV_GAMMA / 1.4426950408889634f);
                hp += wl * net_weights[n];
            }

            // bbox in grid coords
            bxm = (vxm + 1.0f) * 0.5f * (MMG - 1);
            bxM = (vxM + 1.0f) * 0.5f * (MMG - 1);
            bym = (vym + 1.0f) * 0.5f * (MMG - 1);
            byM = (vyM + 1.0f) * 0.5f * (MMG - 1);
            float bsize = fmaxf((bxM - bxm + 1.0f) * (byM - bym + 1.0f), 1.0f);
            inv_bs = __fdividef(1.0f, bsize);
        }

#pragma unroll
        for (int t = 0; t < 2; t++) {
            int gi = lane + t * 32;
            float g = (float)gi;
            float xv = 0.0f, yv = 0.0f;
            if (active) {
                // sig(a)*sig(b) = 1 / ((1+e^-a)(1+e^-b)) : one RCP per pair
                float ex0 = exp2f(KL2 * (bxm - g - 0.5f));
                float ex1 = exp2f(KL2 * (g - bxM - 0.5f));
                float ey0 = exp2f(KL2 * (bym - g - 0.5f));
                float ey1 = exp2f(KL2 * (g - byM - 0.5f));
                xv = __fdividef(1.0f,   (1.0f + ex0) * (1.0f + ex1));
                yv = __fdividef(inv_bs, (1.0f + ey0) * (1.0f + ey1));
            }
            Xs[w][gi] = xv;
            Ys[w][gi] = yv;
        }
        __syncthreads();

        // rank-8 update of 64x64 tile (4x4 per thread)
#pragma unroll
        for (int k = 0; k < 8; k++) {
            float4 yv = *(const float4*)&Ys[k][ty * 4];
            float4 xv = *(const float4*)&Xs[k][tx * 4];
            acc[0][0] = fmaf(yv.x, xv.x, acc[0][0]);
            acc[0][1] = fmaf(yv.x, xv.y, acc[0][1]);
            acc[0][2] = fmaf(yv.x, xv.z, acc[0][2]);
            acc[0][3] = fmaf(yv.x, xv.w, acc[0][3]);
            acc[1][0] = fmaf(yv.y, xv.x, acc[1][0]);
            acc[1][1] = fmaf(yv.y, xv.y, acc[1][1]);
            acc[1][2] = fmaf(yv.y, xv.z, acc[1][2]);
            acc[1][3] = fmaf(yv.y, xv.w, acc[1][3]);
            acc[2][0] = fmaf(yv.z, xv.x, acc[2][0]);
            acc[2][1] = fmaf(yv.z, xv.y, acc[2][1]);
            acc[2][2] = fmaf(yv.z, xv.z, acc[2][2]);
            acc[2][3] = fmaf(yv.z, xv.w, acc[2][3]);
            acc[3][0] = fmaf(yv.w, xv.x, acc[3][0]);
            acc[3][1] = fmaf(yv.w, xv.y, acc[3][1]);
            acc[3][2] = fmaf(yv.w, xv.z, acc[3][2]);
            acc[3][3] = fmaf(yv.w, xv.w, acc[3][3]);
        }
        __syncthreads();
    }

    // flush tile partials
#pragma unroll
    for (int a = 0; a < 4; a++)
#pragma unroll
        for (int c = 0; c < 4; c++)
            atomicAdd(&g_rudy[b][(ty * 4 + a) * MMG + tx * 4 + c], acc[a][c]);

    if (lane == 0) atomicAdd(&g_hpwl[b], hp);
}

// ---------------------------------------------------------------------------
// Phase C: 7x7 Gaussian smooth (zero-padded) + overflow penalty.
// grid (16 slices, B); each block: 4 output rows, 1 cell/thread.
__global__ __launch_bounds__(256) void conv_kernel()
{
    __shared__ float tile[10][MMG];
    __shared__ float red[8];
    const int b     = blockIdx.y;
    const int slice = blockIdx.x;
    const int tid   = threadIdx.x;
    const int r0    = slice * 4;

    for (int i = tid; i < 10 * MMG; i += 256) {
        int rr = r0 - 3 + (i >> 6);
        int cc = i & 63;
        tile[i >> 6][cc] = (rr >= 0 && rr < MMG) ? g_rudy[b][rr * MMG + cc] : 0.0f;
    }
    __syncthreads();

    const float g1[7] = {0.13533528f, 0.41111229f, 0.80073740f, 1.0f,
                         0.80073740f, 0.41111229f, 0.13533528f};
    float s1 = 0.0f;
#pragma unroll
    for (int i = 0; i < 7; i++) s1 += g1[i];
    const float inv_norm = __fdividef(1.0f, s1 * s1);

    const int lr = tid >> 6;       // 0..3
    const int j  = tid & 63;
    float s = 0.0f;
#pragma unroll
    for (int di = -3; di <= 3; di++) {
        float rs = 0.0f;
#pragma unroll
        for (int dj = -3; dj <= 3; dj++) {
            int jj = j + dj;
            if (jj >= 0 && jj < MMG)
                rs = fmaf(g1[dj + 3], tile[lr + 3 + di][jj], rs);
        }
        s = fmaf(g1[di + 3], rs, s);
    }
    s *= inv_norm;
    float ov = fmaxf(s - THRESH_F, 0.0f);
    float pen = ov * ov;

    // block reduce
#pragma unroll
    for (int o = 16; o > 0; o >>= 1)
        pen += __shfl_xor_sync(0xffffffffu, pen, o);
    if ((tid & 31) == 0) red[tid >> 5] = pen;
    __syncthreads();
    if (tid < 8) {
        float v = red[tid];
        v += __shfl_xor_sync(0xffu, v, 4);
        v += __shfl_xor_sync(0xffu, v, 2);
        v += __shfl_xor_sync(0xffu, v, 1);
        if (tid == 0) atomicAdd(&g_pen[b], v);
    }
}

// ---------------------------------------------------------------------------
__global__ void finalize_kernel(float* __restrict__ out)
{
    int b = threadIdx.x;
    if (b < BB)
        out[b] = g_hpwl[b] + W_CONG_F * g_pen[b];
}

// ---------------------------------------------------------------------------
extern "C" void kernel_launch(void* const* d_in, const int* in_sizes, int n_in,
                              void* d_out, int out_size)
{
    const float* positions    = nullptr;
    const int*   net_to_pin   = nullptr;
    const int*   pin_to_macro = nullptr;
    const float* pin_offsets  = nullptr;
    const float* rot_onehot   = nullptr;
    const float* net_weights  = nullptr;

    for (int i = 0; i < n_in; i++) {
        switch (in_sizes[i]) {
            case BB * VV * 2:   positions    = (const float*)d_in[i]; break;
            case NNN * MPP:     net_to_pin   = (const int*)  d_in[i]; break;
            case PP:            pin_to_macro = (const int*)  d_in[i]; break;
            case PP * 2:        pin_offsets  = (const float*)d_in[i]; break;
            case BB * VV * 4:   rot_onehot   = (const float*)d_in[i]; break;
            case NNN:           net_weights  = (const float*)d_in[i]; break;
        }
    }

    pin_pos_kernel<<<(BB * PP + 255) / 256, 256>>>(positions, pin_to_macro,
                                                   pin_offsets, rot_onehot);
    net_kernel<<<dim3(NET_BLOCKS, BB), 256>>>(net_to_pin, net_weights);
    conv_kernel<<<dim3(16, BB), 256>>>();
    finalize_kernel<<<1, BB>>>((float*)d_out);
}

// round 3
// speedup vs baseline: 1.1745x; 1.0350x over previous
#include <cuda_runtime.h>
#include <math.h>

// Problem constants (match reference)
#define BB   4
#define VV   20000
#define PP   400000
#define NNN  50000
#define MPP  32
#define MMG  64            // grid M
#define THRESH_F 1.0f
#define W_CONG_F 0.5f

#define NET_BLOCKS 148     // blocks per batch for phase B

// log2(e) folded constants
#define GL2  14.426950408889634f   // GAMMA * log2(e),  GAMMA = 10
#define KL2  2.8853900817779268f   // K_SOFT * log2(e), K_SOFT = 2
#define LN2_OVER_GAMMA 0.069314718055994531f  // ln(2)/GAMMA

// ---------------- scratch (device globals; no allocation allowed) ----------
__device__ float2 g_pin_pos[BB * PP];          // 12.8 MB
__device__ float  g_rudy[BB][MMG * MMG];       // 64 KB
__device__ float  g_hpwl[BB];
__device__ float  g_pen[BB];
__device__ unsigned g_cnt[BB];

// monotonic float <-> uint encoding for REDUX min/max on floats
__device__ __forceinline__ unsigned fenc(float x) {
    unsigned b = __float_as_uint(x);
    return b ^ (((unsigned)((int)b >> 31)) | 0x80000000u);
}
__device__ __forceinline__ float fdec(unsigned u) {
    unsigned b = u ^ ((~(unsigned)((int)u >> 31)) | 0x80000000u);
    return __uint_as_float(b);
}

// packed f32x2 FMA: d = a*b + d (elementwise on 2 floats in a 64-bit reg)
__device__ __forceinline__ void fma2(unsigned long long& d,
                                     unsigned long long a,
                                     unsigned long long b) {
    asm("fma.rn.f32x2 %0, %1, %2, %0;" : "+l"(d) : "l"(a), "l"(b));
}

// ---------------------------------------------------------------------------
// Phase A: pin positions (also zeroes accumulators for this call)
__global__ __launch_bounds__(256) void pin_pos_kernel(
    const float* __restrict__ positions,      // (B,V,2)
    const int*   __restrict__ pin_to_macro,   // (P,)
    const float* __restrict__ pin_offsets,    // (P,2)
    const float* __restrict__ rot_onehot)     // (B,V,4)
{
    int idx = blockIdx.x * blockDim.x + threadIdx.x;

    if (blockIdx.x < 64) {
        (&g_rudy[0][0])[idx] = 0.0f;
        if (idx < BB) { g_hpwl[idx] = 0.0f; g_pen[idx] = 0.0f; g_cnt[idx] = 0u; }
    }

    if (idx >= BB * PP) return;
    int b = idx / PP;
    int p = idx - b * PP;
    int m = pin_to_macro[p];
    float2 pos = ((const float2*)positions)[b * VV + m];
    float4 oh  = ((const float4*)rot_onehot)[b * VV + m];
    float2 off = ((const float2*)pin_offsets)[p];
    float c = oh.x - oh.z;
    float s = oh.y - oh.w;
    float2 pp;
    pp.x = pos.x + c * off.x - s * off.y;
    pp.y = pos.y + s * off.x + c * off.y;
    g_pin_pos[idx] = pp;
}

// ---------------------------------------------------------------------------
// Phase B: per-net soft-HPWL + bbox + rank-8 RUDY accumulation (f32x2 FMA).
__global__ __launch_bounds__(256) void net_kernel(
    const int*   __restrict__ net_to_pin,     // (NN,MP)
    const float* __restrict__ net_weights)    // (NN,)
{
    __shared__ float  Xs[8][MMG];
    __shared__ float2 Ysd[8][MMG];     // duplicated {y,y} for packed FMA

    const int b    = blockIdx.y;
    const int tid  = threadIdx.x;
    const int w    = tid >> 5;
    const int lane = tid & 31;
    const int ty   = tid >> 4;       // 0..15
    const int tx   = tid & 15;       // 0..15

    const int netsPerBlock = (NNN + NET_BLOCKS - 1) / NET_BLOCKS;   // 338
    const int n0 = blockIdx.x * netsPerBlock;
    const int n1 = min(n0 + netsPerBlock, NNN);

    // per-lane constant factors of the separable sigmoid exponentials
    //   ex0(g) = 2^(KL2*(bxm - g - 0.5)) = Fa * C[t],  C = 2^(KL2*(31.5-g))
    //   ex1(g) = 2^(KL2*(g - bxM - 0.5)) = Fb * D[t],  D = 2^(KL2*(g-32.0))
    float Cf[2], Df[2];
#pragma unroll
    for (int t = 0; t < 2; t++) {
        float g = (float)(lane + t * 32);
        Cf[t] = exp2f(KL2 * (31.5f - g));
        Df[t] = exp2f(KL2 * (g - 32.0f));
    }

    unsigned long long acc[4][2];   // 4 rows x 2 col-pairs (packed f32x2)
#pragma unroll
    for (int a = 0; a < 4; a++) { acc[a][0] = 0ull; acc[a][1] = 0ull; }

    float hp = 0.0f;   // meaningful on lane 0 of each warp

    for (int base = n0; base < n1; base += 8) {
        const int n = base + w;
        const bool active = (n < n1);

        float Fax = 0.f, Fbx = 0.f, Fay = 0.f, Fby = 0.f, inv_bs = 0.f;

        if (active) {
            int j = net_to_pin[n * MPP + lane];
            bool valid = (j >= 0);
            int sj = j < 0 ? 0 : j;
            float2 pp = g_pin_pos[b * PP + sj];
            float px = pp.x, py = pp.y;

            unsigned ex = fenc(px);
            unsigned ey = fenc(py);
            float vxM = fdec(__reduce_max_sync(0xffffffffu, valid ? ex : 0u));
            float vxm = fdec(__reduce_min_sync(0xffffffffu, valid ? ex : 0xffffffffu));
            float vyM = fdec(__reduce_max_sync(0xffffffffu, valid ? ey : 0u));
            float vym = fdec(__reduce_min_sync(0xffffffffu, valid ? ey : 0xffffffffu));

            // LSE sums (invalid lanes contribute exactly 0, matching the
            // reference's -1e9 masking which underflows to 0 after exp)
            float exM = valid ? exp2f( GL2 * (px - vxM)) : 0.0f;
            float exm = valid ? exp2f(-GL2 * (px - vxm)) : 0.0f;
            float eyM = valid ? exp2f( GL2 * (py - vyM)) : 0.0f;
            float eym = valid ? exp2f(-GL2 * (py - vym)) : 0.0f;
#pragma unroll
            for (int o = 16; o > 0; o >>= 1) {
                exM += __shfl_xor_sync(0xffffffffu, exM, o);
                exm += __shfl_xor_sync(0xffffffffu, exm, o);
                eyM += __shfl_xor_sync(0xffffffffu, eyM, o);
                eym += __shfl_xor_sync(0xffffffffu, eym, o);
            }

            if (lane == 0) {
                // single log of the product of the 4 sums (each in (0,32])
                float wl = (vxM - vxm) + (vyM - vym)
                         + __log2f(exM * exm * eyM * eym) * LN2_OVER_GAMMA;
                hp += wl * net_weights[n];
            }

            float bxm = (vxm + 1.0f) * 0.5f * (MMG - 1);
            float bxM = (vxM + 1.0f) * 0.5f * (MMG - 1);
            float bym = (vym + 1.0f) * 0.5f * (MMG - 1);
            float byM = (vyM + 1.0f) * 0.5f * (MMG - 1);
            float bsize = fmaxf((bxM - bxm + 1.0f) * (byM - bym + 1.0f), 1.0f);
            inv_bs = __fdividef(1.0f, bsize);

            // per-net scalar exponential factors (overflow-safe split)
            Fax = exp2f(KL2 * (bxm - 32.0f));
            Fbx = exp2f(KL2 * (31.5f - bxM));
            Fay = exp2f(KL2 * (bym - 32.0f));
            Fby = exp2f(KL2 * (31.5f - byM));
        }

#pragma unroll
        for (int t = 0; t < 2; t++) {
            int gi = lane + t * 32;
            float xv = 0.0f, yv = 0.0f;
            if (active) {
                float ex0 = Fax * Cf[t], ex1 = Fbx * Df[t];
                float ey0 = Fay * Cf[t], ey1 = Fby * Df[t];
                xv = __fdividef(1.0f,   (1.0f + ex0) * (1.0f + ex1));
                yv = __fdividef(inv_bs, (1.0f + ey0) * (1.0f + ey1));
            }
            Xs[w][gi]  = xv;
            Ysd[w][gi] = make_float2(yv, yv);
        }
        __syncthreads();

        // rank-8 update of 64x64 tile, packed f32x2 (4x4 per thread)
#pragma unroll
        for (int k = 0; k < 8; k++) {
            // x: 4 cols = 2 packed pairs
            float4 xv = *(const float4*)&Xs[k][tx * 4];
            unsigned long long xlo = *(const unsigned long long*)&xv.x;
            unsigned long long xhi = *(const unsigned long long*)&xv.z;
            // y duplicated: rows ty*4..ty*4+3 = 4 packed pairs (2 float4)
            float4 ya = *(const float4*)&Ysd[k][ty * 4];       // {y0,y0,y1,y1}
            float4 yb = *(const float4*)&Ysd[k][ty * 4 + 2];   // {y2,y2,y3,y3}
            unsigned long long y0 = *(const unsigned long long*)&ya.x;
            unsigned long long y1 = *(const unsigned long long*)&ya.z;
            unsigned long long y2 = *(const unsigned long long*)&yb.x;
            unsigned long long y3 = *(const unsigned long long*)&yb.z;
            fma2(acc[0][0], y0, xlo); fma2(acc[0][1], y0, xhi);
            fma2(acc[1][0], y1, xlo); fma2(acc[1][1], y1, xhi);
            fma2(acc[2][0], y2, xlo); fma2(acc[2][1], y2, xhi);
            fma2(acc[3][0], y3, xlo); fma2(acc[3][1], y3, xhi);
        }
        __syncthreads();
    }

    // flush tile partials
#pragma unroll
    for (int a = 0; a < 4; a++) {
        float2 lo = *(const float2*)&acc[a][0];
        float2 hi = *(const float2*)&acc[a][1];
        float* dst = &g_rudy[b][(ty * 4 + a) * MMG + tx * 4];
        atomicAdd(dst + 0, lo.x);
        atomicAdd(dst + 1, lo.y);
        atomicAdd(dst + 2, hi.x);
        atomicAdd(dst + 3, hi.y);
    }

    if (lane == 0) atomicAdd(&g_hpwl[b], hp);
}

// ---------------------------------------------------------------------------
// Phase C: 7x7 Gaussian smooth (zero-padded) + overflow penalty + finalize.
// grid (16 slices, B); each block: 4 output rows, 1 cell/thread.
__global__ __launch_bounds__(256) void conv_kernel(float* __restrict__ out)
{
    __shared__ float tile[10][MMG];
    __shared__ float red[8];
    const int b     = blockIdx.y;
    const int slice = blockIdx.x;
    const int tid   = threadIdx.x;
    const int r0    = slice * 4;

    for (int i = tid; i < 10 * MMG; i += 256) {
        int rr = r0 - 3 + (i >> 6);
        int cc = i & 63;
        tile[i >> 6][cc] = (rr >= 0 && rr < MMG) ? g_rudy[b][rr * MMG + cc] : 0.0f;
    }
    __syncthreads();

    const float g1[7] = {0.13533528f, 0.41111229f, 0.80073740f, 1.0f,
                         0.80073740f, 0.41111229f, 0.13533528f};
    float s1 = 0.0f;
#pragma unroll
    for (int i = 0; i < 7; i++) s1 += g1[i];
    const float inv_norm = __fdividef(1.0f, s1 * s1);

    const int lr = tid >> 6;       // 0..3
    const int j  = tid & 63;
    float s = 0.0f;
#pragma unroll
    for (int di = -3; di <= 3; di++) {
        float rs = 0.0f;
#pragma unroll
        for (int dj = -3; dj <= 3; dj++) {
            int jj = j + dj;
            if (jj >= 0 && jj < MMG)
                rs = fmaf(g1[dj + 3], tile[lr + 3 + di][jj], rs);
        }
        s = fmaf(g1[di + 3], rs, s);
    }
    s *= inv_norm;
    float ov = fmaxf(s - THRESH_F, 0.0f);
    float pen = ov * ov;

#pragma unroll
    for (int o = 16; o > 0; o >>= 1)
        pen += __shfl_xor_sync(0xffffffffu, pen, o);
    if ((tid & 31) == 0) red[tid >> 5] = pen;
    __syncthreads();
    if (tid == 0) {
        float v = 0.0f;
#pragma unroll
        for (int i = 0; i < 8; i++) v += red[i];
        atomicAdd(&g_pen[b], v);
        __threadfence();
        unsigned done = atomicAdd(&g_cnt[b], 1u);
        if (done == 15u) {   // last block of this batch: finalize
            __threadfence();
            float p = *((volatile float*)&g_pen[b]);
            float h = *((volatile float*)&g_hpwl[b]);
            out[b] = h + W_CONG_F * p;
        }
    }
}

// ---------------------------------------------------------------------------
extern "C" void kernel_launch(void* const* d_in, const int* in_sizes, int n_in,
                              void* d_out, int out_size)
{
    const float* positions    = nullptr;
    const int*   net_to_pin   = nullptr;
    const int*   pin_to_macro = nullptr;
    const float* pin_offsets  = nullptr;
    const float* rot_onehot   = nullptr;
    const float* net_weights  = nullptr;

    for (int i = 0; i < n_in; i++) {
        switch (in_sizes[i]) {
            case BB * VV * 2:   positions    = (const float*)d_in[i]; break;
            case NNN * MPP:     net_to_pin   = (const int*)  d_in[i]; break;
            case PP:            pin_to_macro = (const int*)  d_in[i]; break;
            case PP * 2:        pin_offsets  = (const float*)d_in[i]; break;
            case BB * VV * 4:   rot_onehot   = (const float*)d_in[i]; break;
            case NNN:           net_weights  = (const float*)d_in[i]; break;
        }
    }

    pin_pos_kernel<<<(BB * PP + 255) / 256, 256>>>(positions, pin_to_macro,
                                                   pin_offsets, rot_onehot);
    net_kernel<<<dim3(NET_BLOCKS, BB), 256>>>(net_to_pin, net_weights);
    conv_kernel<<<dim3(16, BB), 256>>>((float*)d_out);
}

// round 4
// speedup vs baseline: 1.3369x; 1.1383x over previous
#include <cuda_runtime.h>
#include <math.h>

// Problem constants (match reference)
#define BB   4
#define VV   20000
#define PP   400000
#define NNN  50000
#define MPP  32
#define MMG  64            // grid M
#define THRESH_F 1.0f
#define W_CONG_F 0.5f

#define NET_BLOCKS 111     // 111*4 = 444 = 148 SMs * 3 blocks -> one wave

// log2(e) folded constants
#define GL2  14.426950408889634f   // GAMMA * log2(e),  GAMMA = 10
#define KL2  2.8853900817779268f   // K_SOFT * log2(e), K_SOFT = 2
#define LN2_OVER_GAMMA 0.069314718055994531f  // ln(2)/GAMMA

// ---------------- scratch (device globals; no allocation allowed) ----------
__device__ float2 g_pin_pos[BB * PP];          // 12.8 MB
__device__ float  g_rudy[BB][MMG * MMG];       // 64 KB
__device__ float  g_hpwl[BB];
__device__ float  g_pen[BB];
__device__ unsigned g_cnt[BB];

// monotonic float <-> uint encoding for REDUX min/max on floats
__device__ __forceinline__ unsigned fenc(float x) {
    unsigned b = __float_as_uint(x);
    return b ^ (((unsigned)((int)b >> 31)) | 0x80000000u);
}
__device__ __forceinline__ float fdec(unsigned u) {
    unsigned b = u ^ ((~(unsigned)((int)u >> 31)) | 0x80000000u);
    return __uint_as_float(b);
}

__device__ __forceinline__ unsigned to_tf32(float x) {
    unsigned r;
    asm("cvt.rna.tf32.f32 %0, %1;" : "=r"(r) : "f"(x));
    return r;
}

__device__ __forceinline__ void mma_tf32(float& c0, float& c1, float& c2, float& c3,
                                         unsigned a0, unsigned a1, unsigned a2, unsigned a3,
                                         unsigned b0, unsigned b1) {
    asm volatile("mma.sync.aligned.m16n8k8.row.col.f32.tf32.tf32.f32 "
                 "{%0,%1,%2,%3}, {%4,%5,%6,%7}, {%8,%9}, {%0,%1,%2,%3};"
                 : "+f"(c0), "+f"(c1), "+f"(c2), "+f"(c3)
                 : "r"(a0), "r"(a1), "r"(a2), "r"(a3), "r"(b0), "r"(b1));
}

// ---------------------------------------------------------------------------
// Phase A: pin positions (also zeroes accumulators for this call)
__global__ __launch_bounds__(256) void pin_pos_kernel(
    const float* __restrict__ positions,      // (B,V,2)
    const int*   __restrict__ pin_to_macro,   // (P,)
    const float* __restrict__ pin_offsets,    // (P,2)
    const float* __restrict__ rot_onehot)     // (B,V,4)
{
    int idx = blockIdx.x * blockDim.x + threadIdx.x;

    if (blockIdx.x < 64) {
        (&g_rudy[0][0])[idx] = 0.0f;
        if (idx < BB) { g_hpwl[idx] = 0.0f; g_pen[idx] = 0.0f; g_cnt[idx] = 0u; }
    }

    if (idx >= BB * PP) return;
    int b = idx / PP;
    int p = idx - b * PP;
    int m = pin_to_macro[p];
    float2 pos = ((const float2*)positions)[b * VV + m];
    float4 oh  = ((const float4*)rot_onehot)[b * VV + m];
    float2 off = ((const float2*)pin_offsets)[p];
    float c = oh.x - oh.z;
    float s = oh.y - oh.w;
    float2 pp;
    pp.x = pos.x + c * off.x - s * off.y;
    pp.y = pos.y + s * off.x + c * off.y;
    g_pin_pos[idx] = pp;
}

// ---------------------------------------------------------------------------
// Phase B: per-net soft-HPWL + bbox + rank-16 RUDY accumulation via tf32 MMA.
// 8 warps/block; each warp processes 2 nets per chunk (ILP) and owns a
// 16x32 region of the 64x64 output (4 m16n8k8 tiles).
__global__ __launch_bounds__(256) void net_kernel(
    const int*   __restrict__ net_to_pin,     // (NN,MP)
    const float* __restrict__ net_weights)    // (NN,)
{
    __shared__ unsigned XsT[MMG][17];   // [cell][k] tf32 bits, padded stride
    __shared__ unsigned YsT[MMG][17];

    const int b    = blockIdx.y;
    const int tid  = threadIdx.x;
    const int w    = tid >> 5;
    const int lane = tid & 31;
    const int g    = lane >> 2;      // group id 0..7
    const int tg   = lane & 3;       // thread-in-group 0..3
    const int rm   = (w & 3) * 16;   // warp's m (row) origin
    const int cn   = (w >> 2) * 32;  // warp's n (col) origin

    const int netsPerBlock = (NNN + NET_BLOCKS - 1) / NET_BLOCKS;   // 451
    const int n0 = blockIdx.x * netsPerBlock;
    const int n1 = min(n0 + netsPerBlock, NNN);

    // per-lane constant factors of the separable sigmoid exponentials
    float Cf[2], Df[2];
#pragma unroll
    for (int t = 0; t < 2; t++) {
        float gg = (float)(lane + t * 32);
        Cf[t] = exp2f(KL2 * (31.5f - gg));
        Df[t] = exp2f(KL2 * (gg - 32.0f));
    }

    float acc[4][4];   // [n-tile][c0..c3]
#pragma unroll
    for (int nt = 0; nt < 4; nt++)
#pragma unroll
        for (int c = 0; c < 4; c++) acc[nt][c] = 0.0f;

    float hp = 0.0f;   // meaningful on lane 0

    for (int base = n0; base < n1; base += 16) {
        float Fax[2], Fbx[2], Fay[2], Fby[2], ivbs[2];
        bool act[2];

#pragma unroll
        for (int q = 0; q < 2; q++) {
            const int n = base + w + q * 8;
            act[q] = (n < n1);
            Fax[q] = Fbx[q] = Fay[q] = Fby[q] = ivbs[q] = 0.0f;
            if (act[q]) {
                int j = net_to_pin[n * MPP + lane];
                bool valid = (j >= 0);
                int sj = j < 0 ? 0 : j;
                float2 pp = g_pin_pos[b * PP + sj];
                float px = pp.x, py = pp.y;

                unsigned ex = fenc(px);
                unsigned ey = fenc(py);
                float vxM = fdec(__reduce_max_sync(0xffffffffu, valid ? ex : 0u));
                float vxm = fdec(__reduce_min_sync(0xffffffffu, valid ? ex : 0xffffffffu));
                float vyM = fdec(__reduce_max_sync(0xffffffffu, valid ? ey : 0u));
                float vym = fdec(__reduce_min_sync(0xffffffffu, valid ? ey : 0xffffffffu));

                // LSE sums (invalid lanes contribute exactly 0)
                float exM = valid ? exp2f( GL2 * (px - vxM)) : 0.0f;
                float exm = valid ? exp2f(-GL2 * (px - vxm)) : 0.0f;
                float eyM = valid ? exp2f( GL2 * (py - vyM)) : 0.0f;
                float eym = valid ? exp2f(-GL2 * (py - vym)) : 0.0f;
#pragma unroll
                for (int o = 16; o > 0; o >>= 1) {
                    exM += __shfl_xor_sync(0xffffffffu, exM, o);
                    exm += __shfl_xor_sync(0xffffffffu, exm, o);
                    eyM += __shfl_xor_sync(0xffffffffu, eyM, o);
                    eym += __shfl_xor_sync(0xffffffffu, eym, o);
                }

                if (lane == 0) {
                    float wl = (vxM - vxm) + (vyM - vym)
                             + __log2f(exM * exm * eyM * eym) * LN2_OVER_GAMMA;
                    hp += wl * net_weights[n];
                }

                float bxm = (vxm + 1.0f) * 0.5f * (MMG - 1);
                float bxM = (vxM + 1.0f) * 0.5f * (MMG - 1);
                float bym = (vym + 1.0f) * 0.5f * (MMG - 1);
                float byM = (vyM + 1.0f) * 0.5f * (MMG - 1);
                float bsize = fmaxf((bxM - bxm + 1.0f) * (byM - bym + 1.0f), 1.0f);
                ivbs[q] = __fdividef(1.0f, bsize);

                Fax[q] = exp2f(KL2 * (bxm - 32.0f));
                Fbx[q] = exp2f(KL2 * (31.5f - bxM));
                Fay[q] = exp2f(KL2 * (bym - 32.0f));
                Fby[q] = exp2f(KL2 * (31.5f - byM));
            }
        }

#pragma unroll
        for (int t = 0; t < 2; t++) {
            const int gi = lane + t * 32;
#pragma unroll
            for (int q = 0; q < 2; q++) {
                float xv = 0.0f, yv = 0.0f;
                if (act[q]) {
                    float ex0 = fminf(Fax[q] * Cf[t], 1e18f);
                    float ex1 = fminf(Fbx[q] * Df[t], 1e18f);
                    float ey0 = fminf(Fay[q] * Cf[t], 1e18f);
                    float ey1 = fminf(Fby[q] * Df[t], 1e18f);
                    float Px = (1.0f + ex0) * (1.0f + ex1);
                    float Py = (1.0f + ey0) * (1.0f + ey1);
                    float R  = __fdividef(1.0f, Px * Py);
                    xv = Py * R;
                    yv = ivbs[q] * Px * R;
                }
                XsT[gi][w + q * 8] = to_tf32(xv);
                YsT[gi][w + q * 8] = to_tf32(yv);
            }
        }
        __syncthreads();

        // rank-16 update: D[i][j] += sum_k Y[k][i] * X[k][j]
        // A (16x8, row-major) = Y^T slice ; B (8x8, col-major) = X slice
#pragma unroll
        for (int ks = 0; ks < 2; ks++) {
            const int k0 = ks * 8;
            unsigned a0 = YsT[rm + g    ][k0 + tg    ];
            unsigned a1 = YsT[rm + g + 8][k0 + tg    ];
            unsigned a2 = YsT[rm + g    ][k0 + tg + 4];
            unsigned a3 = YsT[rm + g + 8][k0 + tg + 4];
#pragma unroll
            for (int nt = 0; nt < 4; nt++) {
                unsigned b0 = XsT[cn + nt * 8 + g][k0 + tg    ];
                unsigned b1 = XsT[cn + nt * 8 + g][k0 + tg + 4];
                mma_tf32(acc[nt][0], acc[nt][1], acc[nt][2], acc[nt][3],
                         a0, a1, a2, a3, b0, b1);
            }
        }
        __syncthreads();
    }

    // writeback: c0 (r, 2tg), c1 (r, 2tg+1), c2 (r+8, 2tg), c3 (r+8, 2tg+1)
    {
        const int r0 = rm + g;
        const int r1 = rm + g + 8;
#pragma unroll
        for (int nt = 0; nt < 4; nt++) {
            const int col = cn + nt * 8 + 2 * tg;
            atomicAdd(&g_rudy[b][r0 * MMG + col    ], acc[nt][0]);
            atomicAdd(&g_rudy[b][r0 * MMG + col + 1], acc[nt][1]);
            atomicAdd(&g_rudy[b][r1 * MMG + col    ], acc[nt][2]);
            atomicAdd(&g_rudy[b][r1 * MMG + col + 1], acc[nt][3]);
        }
    }

    if (lane == 0) atomicAdd(&g_hpwl[b], hp);
}

// ---------------------------------------------------------------------------
// Phase C: 7x7 Gaussian smooth (zero-padded) + overflow penalty + finalize.
__global__ __launch_bounds__(256) void conv_kernel(float* __restrict__ out)
{
    __shared__ float tile[10][MMG];
    __shared__ float red[8];
    const int b     = blockIdx.y;
    const int slice = blockIdx.x;
    const int tid   = threadIdx.x;
    const int r0    = slice * 4;

    for (int i = tid; i < 10 * MMG; i += 256) {
        int rr = r0 - 3 + (i >> 6);
        int cc = i & 63;
        tile[i >> 6][cc] = (rr >= 0 && rr < MMG) ? g_rudy[b][rr * MMG + cc] : 0.0f;
    }
    __syncthreads();

    const float g1[7] = {0.13533528f, 0.41111229f, 0.80073740f, 1.0f,
                         0.80073740f, 0.41111229f, 0.13533528f};
    float s1 = 0.0f;
#pragma unroll
    for (int i = 0; i < 7; i++) s1 += g1[i];
    const float inv_norm = __fdividef(1.0f, s1 * s1);

    const int lr = tid >> 6;       // 0..3
    const int j  = tid & 63;
    float s = 0.0f;
#pragma unroll
    for (int di = -3; di <= 3; di++) {
        float rs = 0.0f;
#pragma unroll
        for (int dj = -3; dj <= 3; dj++) {
            int jj = j + dj;
            if (jj >= 0 && jj < MMG)
                rs = fmaf(g1[dj + 3], tile[lr + 3 + di][jj], rs);
        }
        s = fmaf(g1[di + 3], rs, s);
    }
    s *= inv_norm;
    float ov = fmaxf(s - THRESH_F, 0.0f);
    float pen = ov * ov;

#pragma unroll
    for (int o = 16; o > 0; o >>= 1)
        pen += __shfl_xor_sync(0xffffffffu, pen, o);
    if ((tid & 31) == 0) red[tid >> 5] = pen;
    __syncthreads();
    if (tid == 0) {
        float v = 0.0f;
#pragma unroll
        for (int i = 0; i < 8; i++) v += red[i];
        atomicAdd(&g_pen[b], v);
        __threadfence();
        unsigned done = atomicAdd(&g_cnt[b], 1u);
        if (done == 15u) {
            __threadfence();
            float p = *((volatile float*)&g_pen[b]);
            float h = *((volatile float*)&g_hpwl[b]);
            out[b] = h + W_CONG_F * p;
        }
    }
}

// ---------------------------------------------------------------------------
extern "C" void kernel_launch(void* const* d_in, const int* in_sizes, int n_in,
                              void* d_out, int out_size)
{
    const float* positions    = nullptr;
    const int*   net_to_pin   = nullptr;
    const int*   pin_to_macro = nullptr;
    const float* pin_offsets  = nullptr;
    const float* rot_onehot   = nullptr;
    const float* net_weights  = nullptr;

    for (int i = 0; i < n_in; i++) {
        switch (in_sizes[i]) {
            case BB * VV * 2:   positions    = (const float*)d_in[i]; break;
            case NNN * MPP:     net_to_pin   = (const int*)  d_in[i]; break;
            case PP:            pin_to_macro = (const int*)  d_in[i]; break;
            case PP * 2:        pin_offsets  = (const float*)d_in[i]; break;
            case BB * VV * 4:   rot_onehot   = (const float*)d_in[i]; break;
            case NNN:           net_weights  = (const float*)d_in[i]; break;
        }
    }

    pin_pos_kernel<<<(BB * PP + 255) / 256, 256>>>(positions, pin_to_macro,
                                                   pin_offsets, rot_onehot);
    net_kernel<<<dim3(NET_BLOCKS, BB), 256>>>(net_to_pin, net_weights);
    conv_kernel<<<dim3(16, BB), 256>>>((float*)d_out);
}